// round 17
// baseline (speedup 1.0000x reference)
#include <cuda_runtime.h>

#define B_   8
#define N_   1024
#define C_   512
#define H_   8
#define D_   64
#define TOPK 16
#define M_   (B_ * N_)          // 8192 rows
#define KV_C (2 * C_)           // 1024
#define NROWS ((size_t)B_ * H_ * N_)   // 65536 score rows

// Scratch (device globals; no allocation allowed)
__device__ float g_q[M_ * C_];          // relu(x@Wq+bq)
__device__ float g_kv[M_ * KV_C];       // x@Wkv+bkv  (k at [0,512), v at [512,1024))
__device__ float g_att[M_ * C_];        // attention output (pre-projection)
__device__ float g_vsum[B_ * H_ * D_];  // per-(b,h) column sums of v
__device__ unsigned g_su[NROWS * N_];   // mono-packed scores, 256MB

// ---------------------------------------------------------------------------
// Tiled fp32 GEMM, double-buffered smem (one barrier per k-tile):
// C = act(A[M,K] @ W[K,Nc] + bias), 128x128 tile, BK=8, 8x8 microtile.
// ---------------------------------------------------------------------------
template <bool RELU>
__global__ __launch_bounds__(256, 2) void gemm_kernel(
    const float* __restrict__ A, const float* __restrict__ W,
    const float* __restrict__ bias, float* __restrict__ Cc, int K, int Nc)
{
    __shared__ float As[2][8][132];
    __shared__ float Bs[2][8][128];

    int tid = threadIdx.x;
    int tx  = tid & 15;
    int ty  = tid >> 4;
    int rowTile = blockIdx.y * 128;
    int colTile = blockIdx.x * 128;

    int arow = tid >> 1;
    int aseg = (tid & 1) * 4;
    int bkr  = tid >> 5;
    int bcol = (tid & 31) * 4;

    const float* Aptr = A + (size_t)(rowTile + arow) * K + aseg;
    const float* Bptr = W + (size_t)bkr * Nc + colTile + bcol;

    float acc[8][8];
#pragma unroll
    for (int i = 0; i < 8; i++)
#pragma unroll
        for (int j = 0; j < 8; j++) acc[i][j] = 0.f;

    // prologue: stage tile 0, prefetch tile 1 into registers
    float4 av = *(const float4*)(Aptr);
    float4 bv = *(const float4*)(Bptr);
    As[0][aseg + 0][arow] = av.x;
    As[0][aseg + 1][arow] = av.y;
    As[0][aseg + 2][arow] = av.z;
    As[0][aseg + 3][arow] = av.w;
    *(float4*)&Bs[0][bkr][bcol] = bv;
    if (8 < K) {
        av = *(const float4*)(Aptr + 8);
        bv = *(const float4*)(Bptr + (size_t)8 * Nc);
    }
    __syncthreads();

    int cur = 0;
    for (int kt = 0; kt < K; kt += 8) {
        if (kt + 8 < K) {
            As[cur ^ 1][aseg + 0][arow] = av.x;
            As[cur ^ 1][aseg + 1][arow] = av.y;
            As[cur ^ 1][aseg + 2][arow] = av.z;
            As[cur ^ 1][aseg + 3][arow] = av.w;
            *(float4*)&Bs[cur ^ 1][bkr][bcol] = bv;
            if (kt + 16 < K) {   // prefetch tile kt+16 (overlaps compute below)
                av = *(const float4*)(Aptr + kt + 16);
                bv = *(const float4*)(Bptr + (size_t)(kt + 16) * Nc);
            }
        }
#pragma unroll
        for (int kk = 0; kk < 8; kk++) {
            float a[8], b[8];
            *(float4*)(a)     = *(const float4*)&As[cur][kk][ty * 8];
            *(float4*)(a + 4) = *(const float4*)&As[cur][kk][ty * 8 + 4];
            *(float4*)(b)     = *(const float4*)&Bs[cur][kk][tx * 8];
            *(float4*)(b + 4) = *(const float4*)&Bs[cur][kk][tx * 8 + 4];
#pragma unroll
            for (int i = 0; i < 8; i++)
#pragma unroll
                for (int j = 0; j < 8; j++)
                    acc[i][j] += a[i] * b[j];
        }
        __syncthreads();
        cur ^= 1;
    }

#pragma unroll
    for (int i = 0; i < 8; i++) {
        float* crow = Cc + (size_t)(rowTile + ty * 8 + i) * Nc + colTile + tx * 8;
#pragma unroll
        for (int j = 0; j < 8; j += 4) {
            float4 o;
            o.x = acc[i][j + 0] + bias[colTile + tx * 8 + j + 0];
            o.y = acc[i][j + 1] + bias[colTile + tx * 8 + j + 1];
            o.z = acc[i][j + 2] + bias[colTile + tx * 8 + j + 2];
            o.w = acc[i][j + 3] + bias[colTile + tx * 8 + j + 3];
            if (RELU) {
                o.x = fmaxf(o.x, 0.f); o.y = fmaxf(o.y, 0.f);
                o.z = fmaxf(o.z, 0.f); o.w = fmaxf(o.w, 0.f);
            }
            *(float4*)(crow + j) = o;
        }
    }
}

// ---------------------------------------------------------------------------
// vsum[b,h,d] = sum_n v[b,h,n,d]
// ---------------------------------------------------------------------------
__global__ __launch_bounds__(256) void vsum_kernel(float* __restrict__ vs)
{
    __shared__ float red[256];
    int bh = blockIdx.x;
    int b = bh >> 3, h = bh & 7;
    int tid = threadIdx.x;
    int d = tid & 63, chunk = tid >> 6;

    size_t base = ((size_t)b * N_) * KV_C + C_ + (size_t)h * D_ + d;
    float s = 0.f;
    int n0 = chunk * 256;
    for (int n = n0; n < n0 + 256; n++)
        s += g_kv[base + (size_t)n * KV_C];
    red[tid] = s;
    __syncthreads();
    if (chunk == 0)
        vs[bh * 64 + d] = red[d] + red[d + 64] + red[d + 128] + red[d + 192];
}

// ---------------------------------------------------------------------------
// Full-precision monotonic float<->uint mapping (bijective, order-preserving).
// ---------------------------------------------------------------------------
__device__ __forceinline__ unsigned mono_pack(float s)
{
    unsigned b = __float_as_uint(s);
    return b ^ (unsigned)(((int)b >> 31) | 0x80000000);
}
__device__ __forceinline__ float mono_unpack(unsigned u)
{
    unsigned b = (u & 0x80000000u) ? (u ^ 0x80000000u) : ~u;
    return __uint_as_float(b);
}

// ---------------------------------------------------------------------------
// scores_kernel: 64 q-rows x 1024 keys per block, double-buffered k staging.
// bh0 selects the bh half so scores/topk can pipeline across streams.
// ---------------------------------------------------------------------------
#define SROWS 64
#define QT_PITCH 66
#define KST_PITCH 132
#define SC_SMEM_BYTES ((64 * QT_PITCH + 2 * 64 * KST_PITCH) * 4)

__global__ __launch_bounds__(256, 2) void scores_kernel(int bh0)
{
    extern __shared__ float sm[];
    float* qT  = sm;                    // [64][66]  qT[d][r]
    float* kst = qT + 64 * QT_PITCH;    // [2][64][132] kst[buf][d][m]

    int bh = blockIdx.y + bh0;
    int b = bh >> 3, h = bh & 7;
    int n0 = blockIdx.x * SROWS;
    int tid = threadIdx.x;
    int w    = tid >> 5;                // warp 0..7 -> rows 8w..8w+7
    int lane = tid & 31;                // cols 4*lane..4*lane+3 per tile
    const float scale = 0.125f;

    // load 64 q rows transposed (coalesced LDG)
    {
        size_t qbase = ((size_t)(b * N_ + n0)) * C_ + (size_t)h * D_;
        for (int f = tid; f < SROWS * 64; f += 256) {
            int r = f >> 6, d = f & 63;
            qT[d * QT_PITCH + r] = g_q[qbase + (size_t)r * C_ + d];
        }
    }

    size_t kbase = ((size_t)b * N_) * KV_C + (size_t)h * D_;
    size_t rowbase = ((size_t)bh * N_ + n0);

    // prologue: load tile 0, stage into buf 0, prefetch tile 1
    float4 pf[8];
#pragma unroll
    for (int i = 0; i < 8; i++) {
        int g = tid + 256 * i;
        int m = g & 127, d4 = (g >> 7) * 4;
        pf[i] = *(const float4*)&g_kv[kbase + (size_t)m * KV_C + d4];
    }
#pragma unroll
    for (int i = 0; i < 8; i++) {
        int g = tid + 256 * i;
        int m = g & 127, d4 = (g >> 7) * 4;
        kst[(d4 + 0) * KST_PITCH + m] = pf[i].x;
        kst[(d4 + 1) * KST_PITCH + m] = pf[i].y;
        kst[(d4 + 2) * KST_PITCH + m] = pf[i].z;
        kst[(d4 + 3) * KST_PITCH + m] = pf[i].w;
    }
#pragma unroll
    for (int i = 0; i < 8; i++) {
        int g = tid + 256 * i;
        int m = g & 127, d4 = (g >> 7) * 4;
        pf[i] = *(const float4*)&g_kv[kbase + (size_t)(128 + m) * KV_C + d4];
    }
    __syncthreads();

    int cur = 0;
    for (int mt = 0; mt < N_; mt += 128) {
        float* kc = kst + cur * 64 * KST_PITCH;
        if (mt + 128 < N_) {
            float* kn = kst + (cur ^ 1) * 64 * KST_PITCH;
#pragma unroll
            for (int i = 0; i < 8; i++) {
                int g = tid + 256 * i;
                int m = g & 127, d4 = (g >> 7) * 4;
                kn[(d4 + 0) * KST_PITCH + m] = pf[i].x;
                kn[(d4 + 1) * KST_PITCH + m] = pf[i].y;
                kn[(d4 + 2) * KST_PITCH + m] = pf[i].z;
                kn[(d4 + 3) * KST_PITCH + m] = pf[i].w;
            }
            if (mt + 256 < N_) {
#pragma unroll
                for (int i = 0; i < 8; i++) {
                    int g = tid + 256 * i;
                    int m = g & 127, d4 = (g >> 7) * 4;
                    pf[i] = *(const float4*)&g_kv[kbase + (size_t)(mt + 256 + m) * KV_C + d4];
                }
            }
        }

        float acc[8][4];
#pragma unroll
        for (int r = 0; r < 8; r++)
#pragma unroll
            for (int c = 0; c < 4; c++) acc[r][c] = 0.f;

        const float* qTw = qT + 8 * w;          // even offset -> 8B aligned
#pragma unroll 4
        for (int d = 0; d < 64; d++) {
            float4 k4 = *(const float4*)&kc[d * KST_PITCH + 4 * lane];
            float2 q01 = *(const float2*)&qTw[d * QT_PITCH + 0];  // broadcast
            float2 q23 = *(const float2*)&qTw[d * QT_PITCH + 2];
            float2 q45 = *(const float2*)&qTw[d * QT_PITCH + 4];
            float2 q67 = *(const float2*)&qTw[d * QT_PITCH + 6];
            float q[8] = {q01.x, q01.y, q23.x, q23.y, q45.x, q45.y, q67.x, q67.y};
#pragma unroll
            for (int r = 0; r < 8; r++) {
                acc[r][0] += q[r] * k4.x; acc[r][1] += q[r] * k4.y;
                acc[r][2] += q[r] * k4.z; acc[r][3] += q[r] * k4.w;
            }
        }

#pragma unroll
        for (int r = 0; r < 8; r++) {
            uint4 p;
            p.x = mono_pack(acc[r][0] * scale);
            p.y = mono_pack(acc[r][1] * scale);
            p.z = mono_pack(acc[r][2] * scale);
            p.w = mono_pack(acc[r][3] * scale);
            *(uint4*)&g_su[(rowbase + 8 * w + r) * N_ + mt + 4 * lane] = p;
        }
        __syncthreads();
        cur ^= 1;
    }
}

// ---------------------------------------------------------------------------
// topk_kernel: 1 warp per score row (rows offset by blk0*8), no smem.
// Exact uint-argmax top-16, closed-form sparse softmax, gather epilogue.
// ---------------------------------------------------------------------------
__global__ __launch_bounds__(256) void topk_kernel(const float* __restrict__ vs,
                                                   int blk0)
{
    size_t row = (size_t)(blockIdx.x + blk0) * 8 + (threadIdx.x >> 5);
    int lane = threadIdx.x & 31;
    int bh = (int)(row >> 10);
    int n  = (int)(row & 1023);
    int b = bh >> 3, h = bh & 7;

    const unsigned* srow = g_su + row * N_;

    unsigned v[32];
#pragma unroll
    for (int i = 0; i < 8; i++) {
        uint4 p = *(const uint4*)&srow[4 * lane + 128 * i];
        v[4 * i + 0] = (p.x & ~31u) | (unsigned)(4 * i + 0);
        v[4 * i + 1] = (p.y & ~31u) | (unsigned)(4 * i + 1);
        v[4 * i + 2] = (p.z & ~31u) | (unsigned)(4 * i + 2);
        v[4 * i + 3] = (p.w & ~31u) | (unsigned)(4 * i + 3);
    }

    int selidx = 0;
#pragma unroll
    for (int it = 0; it < TOPK; it++) {
        unsigned lm = v[0];
#pragma unroll
        for (int j = 1; j < 32; j++) lm = max(lm, v[j]);
        unsigned gm = __reduce_max_sync(0xffffffffu, lm);
        unsigned ball = __ballot_sync(0xffffffffu, lm == gm);
        int wl = __ffs(ball) - 1;
        int jj = (int)(gm & 31u);
        if (lane == it)
            selidx = 4 * wl + 128 * (jj >> 2) + (jj & 3);
        if (lane == wl) {
#pragma unroll
            for (int j = 0; j < 32; j++)
                if (j == jj) v[j] = 0u;
        }
    }

    float sv = 0.f;
    if (lane < TOPK) sv = mono_unpack(srow[selidx]);
    float s0 = __shfl_sync(0xffffffffu, sv, 0);
    float Mx = fmaxf(0.f, s0);
    float c  = expf(-Mx);
    float ww = (lane < TOPK) ? expf(sv - Mx) : 0.f;
    float s = ww;
#pragma unroll
    for (int off = 16; off; off >>= 1)
        s += __shfl_xor_sync(0xffffffffu, s, off);
    float Z = s + (float)(N_ - TOPK) * c;
    float wfin = (ww - c) / Z;
    float cz = c / Z;

    size_t vbase = ((size_t)b * N_) * KV_C + C_ + (size_t)h * D_ + 2 * lane;
    float2 o = make_float2(0.f, 0.f);
#pragma unroll
    for (int i = 0; i < TOPK; i++) {
        float wi = __shfl_sync(0xffffffffu, wfin, i);
        int   ii = __shfl_sync(0xffffffffu, selidx, i);
        float2 vv = *(const float2*)&g_kv[vbase + (size_t)ii * KV_C];
        o.x += wi * vv.x; o.y += wi * vv.y;
    }
    float2 sv2 = *(const float2*)&vs[bh * 64 + 2 * lane];
    o.x += cz * sv2.x; o.y += cz * sv2.y;
    *(float2*)&g_att[((size_t)(b * N_ + n)) * C_ + (size_t)h * D_ + 2 * lane] = o;
}

// ---------------------------------------------------------------------------
// Launch schedule (DAG, 2 side streams forked off the capture-origin stream):
//   s1: Q-gemm ............ -> scores_A -> scores_B
//   s2: KV-gemm -> vsum ... -> topk_A (|| scores_B) -> topk_B
//   0 : fork ................................... join -> P-gemm
// ---------------------------------------------------------------------------
extern "C" void kernel_launch(void* const* d_in, const int* in_sizes, int n_in,
                              void* d_out, int out_size)
{
    const float* x   = (const float*)d_in[0];
    const float* Wq  = (const float*)d_in[1];
    const float* bq  = (const float*)d_in[2];
    const float* Wkv = (const float*)d_in[3];
    const float* bkv = (const float*)d_in[4];
    const float* Wp  = (const float*)d_in[5];
    const float* bp  = (const float*)d_in[6];
    float* out = (float*)d_out;

    float *gq, *gkv, *gatt, *gvs;
    cudaGetSymbolAddress((void**)&gq,  g_q);
    cudaGetSymbolAddress((void**)&gkv, g_kv);
    cudaGetSymbolAddress((void**)&gatt, g_att);
    cudaGetSymbolAddress((void**)&gvs, g_vsum);

    // one-time infra (created on the uncaptured correctness call; reused after)
    static cudaStream_t s1 = nullptr, s2 = nullptr;
    static cudaEvent_t eFork, eKV, eSA, eSB, eT;
    if (!s1) {
        cudaStreamCreateWithFlags(&s1, cudaStreamNonBlocking);
        cudaStreamCreateWithFlags(&s2, cudaStreamNonBlocking);
        cudaEventCreateWithFlags(&eFork, cudaEventDisableTiming);
        cudaEventCreateWithFlags(&eKV,   cudaEventDisableTiming);
        cudaEventCreateWithFlags(&eSA,   cudaEventDisableTiming);
        cudaEventCreateWithFlags(&eSB,   cudaEventDisableTiming);
        cudaEventCreateWithFlags(&eT,    cudaEventDisableTiming);
        cudaFuncSetAttribute(scores_kernel,
                             cudaFuncAttributeMaxDynamicSharedMemorySize,
                             SC_SMEM_BYTES);
    }

    // fork both side streams from the capture-origin (default) stream
    cudaEventRecord(eFork, (cudaStream_t)0);
    cudaStreamWaitEvent(s1, eFork, 0);
    cudaStreamWaitEvent(s2, eFork, 0);

    // s1: Q = relu(x @ Wq + bq)
    gemm_kernel<true><<<dim3(C_ / 128, M_ / 128), 256, 0, s1>>>(x, Wq, bq, gq, C_, C_);
    // s2: KV = x @ Wkv + bkv, then vsum
    gemm_kernel<false><<<dim3(KV_C / 128, M_ / 128), 256, 0, s2>>>(x, Wkv, bkv, gkv, C_, KV_C);
    cudaEventRecord(eKV, s2);
    vsum_kernel<<<B_ * H_, 256, 0, s2>>>(gvs);

    // s1: scores (needs Q in-stream + KV via event), split into two bh halves
    cudaStreamWaitEvent(s1, eKV, 0);
    scores_kernel<<<dim3(N_ / SROWS, 32), 256, SC_SMEM_BYTES, s1>>>(0);
    cudaEventRecord(eSA, s1);
    scores_kernel<<<dim3(N_ / SROWS, 32), 256, SC_SMEM_BYTES, s1>>>(32);
    cudaEventRecord(eSB, s1);

    // s2: topk halves; topk_A overlaps scores_B
    cudaStreamWaitEvent(s2, eSA, 0);
    topk_kernel<<<4096, 256, 0, s2>>>(gvs, 0);
    cudaStreamWaitEvent(s2, eSB, 0);
    topk_kernel<<<4096, 256, 0, s2>>>(gvs, 4096);
    cudaEventRecord(eT, s2);

    // join back to origin stream, then final projection
    cudaStreamWaitEvent((cudaStream_t)0, eT, 0);
    gemm_kernel<false><<<dim3(C_ / 128, M_ / 128), 256>>>(gatt, Wp, bp, out, C_, C_);
}